// round 15
// baseline (speedup 1.0000x reference)
#include <cuda_runtime.h>

#define NN 50000
#define EE 800000
#define PP 12
#define NTILES 1563          // ceil(NN/32)
#define GB 444               // 148 SMs * 3 blocks — co-resident persistent grid
#define CAP 64               // bucket capacity (max in-degree ~40 for this graph)

typedef unsigned long long u64;

// ---------------- scratch (device globals; no allocation) ----------------
__device__ int    g_cnt[NN];             // in-edge count per node (padded to x4 after P2)
__device__ float  g_dinv[NN];
__device__ unsigned g_count;             // grid barrier counter
__device__ int2   g_rec[NN * CAP];       // bucketed records {row, ew-bits}
__device__ ulonglong2 g_xT32[NN * 24];   // fp32 features: [n][h][sub] float4
__device__ float  g_H[NN * 64];          // relu(H_accum)
__device__ float  g_sums[64];
__device__ float  g_sumsq[64];
__device__ float  g_Az[8 * 64], g_Ah[8 * 64];   // Az, cz pre-folded by 0.5
__device__ float  g_cz[64], g_ch[64];
__device__ float  g_probs[PP];
__device__ float  g_Wc[64 * 96], g_bc[96];

__device__ __forceinline__ float tanha(float x) {
    float r; asm("tanh.approx.f32 %0, %1;" : "=f"(r) : "f"(x)); return r;
}
__device__ __forceinline__ u64 pk(float x, float y) {
    u64 r; asm("mov.b64 %0, {%1, %2};" : "=l"(r) : "f"(x), "f"(y)); return r;
}
__device__ __forceinline__ void upk(u64 v, float& x, float& y) {
    asm("mov.b64 {%0, %1}, %2;" : "=f"(x), "=f"(y) : "l"(v));
}
__device__ __forceinline__ u64 ffma2(u64 a, u64 b, u64 c) {
    u64 d; asm("fma.rn.f32x2 %0, %1, %2, %3;" : "=l"(d) : "l"(a), "l"(b), "l"(c)); return d;
}
__device__ __forceinline__ u64 fadd2(u64 a, u64 b) {
    u64 d; asm("add.rn.f32x2 %0, %1, %2;" : "=l"(d) : "l"(a), "l"(b)); return d;
}
__device__ __forceinline__ u64 fmul2(u64 a, u64 b) {
    u64 d; asm("mul.rn.f32x2 %0, %1, %2;" : "=l"(d) : "l"(a), "l"(b)); return d;
}

// monotonic-counter grid barrier; k = 1,2,3,... within one kernel run
__device__ __forceinline__ void gbar(int k) {
    __syncthreads();
    if (threadIdx.x == 0) {
        __threadfence();
        atomicAdd(&g_count, 1u);
        while (*(volatile unsigned*)&g_count < (unsigned)(GB * k)) __nanosleep(32);
        __threadfence();
    }
    __syncthreads();
}

// ---------------- kernel A: reset barrier counter --------------------------
__global__ void k_reset() { g_count = 0u; }

// ---------------- kernel B: the whole pipeline, one persistent grid --------
__global__ void __launch_bounds__(256, 3) k_mega(
        const float* __restrict__ x,
        const int*   __restrict__ ei,
        const float* __restrict__ ew,
        const float* __restrict__ att,
        const float* __restrict__ conv_w, const float* __restrict__ conv_b,
        const float* __restrict__ lin_w,  const float* __restrict__ lin_b,
        const float* __restrict__ gamma,  const float* __restrict__ beta,
        const float* __restrict__ W1, const float* __restrict__ b1,
        const float* __restrict__ W2, const float* __restrict__ b2,
        const float* __restrict__ W3, const float* __restrict__ b3,
        const float* __restrict__ W4, const float* __restrict__ b4,
        const float* __restrict__ W5, const float* __restrict__ b5,
        float* __restrict__ out) {
    __shared__ __align__(16) char smraw[38912];
    int tid = threadIdx.x, bid = blockIdx.x;

    // ================= P0: init cnt + transpose x + fold weights ===========
    {
        for (int i = bid * 256 + tid; i < NN; i += GB * 256)
            g_cnt[i] = 0;

        float* s = (float*)smraw;                 // 32*96 floats = 12KB
        for (int tile = bid; tile < NTILES; tile += GB) {
            int blockNode = tile * 32;
            int lim = (NN - blockNode) * 96;
            __syncthreads();
            for (int i = tid; i < 32 * 96; i += 256)
                s[i] = (i < lim) ? x[blockNode * 96 + i] : 0.f;
            __syncthreads();
            #pragma unroll
            for (int k = 0; k < 3; k++) {
                int o = tid + k * 256;            // 0..767 = 32 nodes * 24 float4
                int ln = o / 24, l = o - ln * 24;
                int n = blockNode + ln;
                if (n < NN) {
                    int h = l / 12, sub = l - h * 12;
                    float4 v;
                    v.x = s[ln * 96 + (h * 4 + 0) * 12 + sub];
                    v.y = s[ln * 96 + (h * 4 + 1) * 12 + sub];
                    v.z = s[ln * 96 + (h * 4 + 2) * 12 + sub];
                    v.w = s[ln * 96 + (h * 4 + 3) * 12 + sub];
                    *(float4*)&g_xT32[n * 24 + h * 12 + sub] = v;
                }
            }
        }

        if (bid == GB - 1) {
            __syncthreads();
            float* sT1 = (float*)smraw;           // 2048 floats
            float* sT2 = sT1 + 2048;              // 1024
            float* sT3 = sT2 + 1024;              // 512
            float* sbb = sT3 + 512;               // 56

            if (tid == 0) {
                float m = -1e30f;
                for (int i = 0; i < PP; i++) m = fmaxf(m, att[i]);
                float e[PP], ssum = 0.f;
                for (int i = 0; i < PP; i++) { e[i] = __expf(att[i] - m); ssum += e[i]; }
                for (int i = 0; i < PP; i++) g_probs[i] = e[i] / ssum;
            }
            for (int idx = tid; idx < 8 * 64; idx += 256) {
                int i = idx >> 6, j = idx & 63;
                float az = 0.f, ah = 0.f;
                for (int k = 0; k < 64; k++) {
                    az += conv_w[0 * 512 + i * 64 + k] * lin_w[0 * 8192 + k * 64 + j];
                    ah += conv_w[2 * 512 + i * 64 + k] * lin_w[2 * 8192 + k * 64 + j];
                }
                g_Az[idx] = 0.5f * az; g_Ah[idx] = ah;
            }
            for (int j = tid; j < 64; j += 256) {
                float cz = lin_b[0 * 64 + j], ch = lin_b[2 * 64 + j];
                for (int k = 0; k < 64; k++) {
                    cz += conv_b[0 * 64 + k] * lin_w[0 * 8192 + k * 64 + j];
                    ch += conv_b[2 * 64 + k] * lin_w[2 * 8192 + k * 64 + j];
                }
                g_cz[j] = 0.5f * cz; g_ch[j] = ch;
                g_sums[j] = 0.f; g_sumsq[j] = 0.f;
            }
            for (int idx = tid; idx < 64 * 32; idx += 256) {
                int i = idx >> 5, j = idx & 31; float s2 = 0.f;
                for (int k = 0; k < 64; k++) s2 += W1[i * 64 + k] * W2[k * 32 + j];
                sT1[idx] = s2;
            }
            if (tid < 32) { float s2 = b2[tid]; for (int k = 0; k < 64; k++) s2 += b1[k] * W2[k * 32 + tid]; sbb[tid] = s2; }
            __syncthreads();
            for (int idx = tid; idx < 64 * 16; idx += 256) {
                int i = idx >> 4, j = idx & 15; float s2 = 0.f;
                for (int k = 0; k < 32; k++) s2 += sT1[i * 32 + k] * W3[k * 16 + j];
                sT2[idx] = s2;
            }
            if (tid < 16) { float s2 = b3[tid]; for (int k = 0; k < 32; k++) s2 += sbb[k] * W3[k * 16 + tid]; sbb[32 + tid] = s2; }
            __syncthreads();
            for (int idx = tid; idx < 64 * 8; idx += 256) {
                int i = idx >> 3, j = idx & 7; float s2 = 0.f;
                for (int k = 0; k < 16; k++) s2 += sT2[i * 16 + k] * W4[k * 8 + j];
                sT3[idx] = s2;
            }
            if (tid < 8) { float s2 = b4[tid]; for (int k = 0; k < 16; k++) s2 += sbb[32 + k] * W4[k * 8 + tid]; sbb[48 + tid] = s2; }
            __syncthreads();
            for (int idx = tid; idx < 64 * 96; idx += 256) {
                int i = idx / 96, j = idx - i * 96; float s2 = 0.f;
                for (int k = 0; k < 8; k++) s2 += sT3[i * 8 + k] * W5[k * 96 + j];
                g_Wc[idx] = s2;
            }
            for (int j = tid; j < 96; j += 256) {
                float s2 = b5[j];
                for (int k = 0; k < 8; k++) s2 += sbb[48 + k] * W5[k * 96 + j];
                g_bc[j] = s2;
            }
        }
    }
    gbar(1);

    // ================= P1: bucket fill {row, ew} (2 edges/iter) ============
    for (int e = (bid * 256 + tid) * 2; e < EE; e += GB * 256 * 2) {
        int2 rows = *(const int2*)&ei[e];
        int2 cols = *(const int2*)&ei[EE + e];
        float2 w = *(const float2*)&ew[e];
        int p0 = atomicAdd(&g_cnt[cols.x], 1);
        if (p0 < CAP) g_rec[cols.x * CAP + p0] = make_int2(rows.x, __float_as_int(w.x));
        int p1 = atomicAdd(&g_cnt[cols.y], 1);
        if (p1 < CAP) g_rec[cols.y * CAP + p1] = make_int2(rows.y, __float_as_int(w.y));
    }
    gbar(2);

    // ================= P2: degree -> dinv, pad bucket to multiple of 4 =====
    for (int n = bid * 256 + tid; n < NN; n += GB * 256) {
        int cnt = g_cnt[n];
        if (cnt > CAP) cnt = CAP;
        int2* rec = &g_rec[n * CAP];
        float s = 1.0f;                          // self-loop weight
        for (int j = 0; j < cnt; j++) s += __int_as_float(rec[j].y);
        g_dinv[n] = rsqrtf(s);
        int cnt4 = (cnt + 3) & ~3;               // pad with zero-weight self records
        for (int j = cnt; j < cnt4; j++) rec[j] = make_int2(n, 0);
        g_cnt[n] = cnt4;
    }
    gbar(3);

    // ================= P3: fused gather + GRU + BN stats ===================
    // 8 lanes per edge, 4 edges per iteration, record+dinv prefetched 1 iter ahead.
    {
        float* bsum = (float*)smraw;             // 64
        float* bsq  = bsum + 64;                 // 64
        float* tw   = bsq + 64;                  // 8 warps * 96
        if (tid < 64) { bsum[tid] = 0.f; bsq[tid] = 0.f; }
        __syncthreads();

        int lane = tid & 31;
        int warp = tid >> 5;
        int g  = lane >> 3;                      // edge-in-quad 0..3
        int l3 = (lane & 7) * 3;                 // first chunk (0,3,...,21)
        float* twr = tw + warp * 96;             // linear layout: chunk c -> floats [4c..4c+3]

        u64 az2[8], ah2[8];
        #pragma unroll
        for (int i = 0; i < 8; i++) {
            az2[i] = *(const u64*)&g_Az[i * 64 + 2 * lane];
            ah2[i] = *(const u64*)&g_Ah[i * 64 + 2 * lane];
        }
        u64 cz2 = *(const u64*)&g_cz[2 * lane];
        u64 ch2 = *(const u64*)&g_ch[2 * lane];

        float psx = 0.f, psy = 0.f, pqx = 0.f, pqy = 0.f;

        for (int n = bid * 8 + warp; n < NN; n += GB * 8) {
            float dn = g_dinv[n];
            int cnt4 = g_cnt[n];                 // padded to x4, <= CAP
            int start = n * CAP;
            int end = start + cnt4;

            u64 a0 = 0, a1 = 0, a2 = 0, a3 = 0, a4 = 0, a5 = 0;
            {   // self term, quarter-coeff in every group (sums to dn over 4 groups)
                const ulonglong2* bp = g_xT32 + n * 24 + l3;
                ulonglong2 v0 = bp[0], v1 = bp[1], v2 = bp[2];
                float fq = 0.25f * dn;
                u64 c = pk(fq, fq);
                a0 = ffma2(v0.x, c, a0); a1 = ffma2(v0.y, c, a1);
                a2 = ffma2(v1.x, c, a2); a3 = ffma2(v1.y, c, a3);
                a4 = ffma2(v2.x, c, a4); a5 = ffma2(v2.y, c, a5);
            }

            // prefetch-pipelined quad loop (record+dinv 1 iteration ahead)
            int2 r = g_rec[start + g];
            float dv = g_dinv[r.x];
            for (int e = start; e < end; e += 4) {
                int2 rc = r;
                float dvc = dv;
                int pe = (e + 4 < end) ? (e + 4) : e;
                r = g_rec[pe + g];
                dv = g_dinv[r.x];
                float f = __int_as_float(rc.y) * dvc;
                const ulonglong2* bp = g_xT32 + rc.x * 24 + l3;
                ulonglong2 v0 = bp[0], v1 = bp[1], v2 = bp[2];
                u64 c = pk(f, f);
                a0 = ffma2(v0.x, c, a0); a1 = ffma2(v0.y, c, a1);
                a2 = ffma2(v1.x, c, a2); a3 = ffma2(v1.y, c, a3);
                a4 = ffma2(v2.x, c, a4); a5 = ffma2(v2.y, c, a5);
            }

            // reduce over 4 edge groups (lanes l, l+8, l+16, l+24), apply dinv[n]
            a0 = fadd2(a0, __shfl_down_sync(0xffffffffu, a0, 16));
            a1 = fadd2(a1, __shfl_down_sync(0xffffffffu, a1, 16));
            a2 = fadd2(a2, __shfl_down_sync(0xffffffffu, a2, 16));
            a3 = fadd2(a3, __shfl_down_sync(0xffffffffu, a3, 16));
            a4 = fadd2(a4, __shfl_down_sync(0xffffffffu, a4, 16));
            a5 = fadd2(a5, __shfl_down_sync(0xffffffffu, a5, 16));
            a0 = fadd2(a0, __shfl_down_sync(0xffffffffu, a0, 8));
            a1 = fadd2(a1, __shfl_down_sync(0xffffffffu, a1, 8));
            a2 = fadd2(a2, __shfl_down_sync(0xffffffffu, a2, 8));
            a3 = fadd2(a3, __shfl_down_sync(0xffffffffu, a3, 8));
            a4 = fadd2(a4, __shfl_down_sync(0xffffffffu, a4, 8));
            a5 = fadd2(a5, __shfl_down_sync(0xffffffffu, a5, 8));
            u64 d2 = pk(dn, dn);
            a0 = fmul2(a0, d2); a1 = fmul2(a1, d2);
            a2 = fmul2(a2, d2); a3 = fmul2(a3, d2);
            a4 = fmul2(a4, d2); a5 = fmul2(a5, d2);

            __syncwarp();
            if (lane < 8) {
                ulonglong2* dst = (ulonglong2*)twr;   // chunk c at dst[c]
                dst[l3 + 0] = make_ulonglong2(a0, a1);
                dst[l3 + 1] = make_ulonglong2(a2, a3);
                dst[l3 + 2] = make_ulonglong2(a4, a5);
            }
            __syncwarp();

            float hx = 0.f, hy = 0.f;
            #pragma unroll
            for (int p = 0; p < PP; p++) {
                float4 uA = *(const float4*)&twr[p * 4];           // chunk p (h0)
                float4 uB = *(const float4*)&twr[(12 + p) * 4];    // chunk 12+p (h1)
                // split even/odd chains: depth 8 -> 4, ILP 2 -> 4
                u64 aE = cz2, aO = 0, bE = ch2, bO = 0;
                u64 s0 = pk(uA.x, uA.x); aE = ffma2(az2[0], s0, aE); bE = ffma2(ah2[0], s0, bE);
                u64 s1 = pk(uA.y, uA.y); aO = ffma2(az2[1], s1, aO); bO = ffma2(ah2[1], s1, bO);
                u64 s2 = pk(uA.z, uA.z); aE = ffma2(az2[2], s2, aE); bE = ffma2(ah2[2], s2, bE);
                u64 s3 = pk(uA.w, uA.w); aO = ffma2(az2[3], s3, aO); bO = ffma2(ah2[3], s3, bO);
                u64 s4 = pk(uB.x, uB.x); aE = ffma2(az2[4], s4, aE); bE = ffma2(ah2[4], s4, bE);
                u64 s5 = pk(uB.y, uB.y); aO = ffma2(az2[5], s5, aO); bO = ffma2(ah2[5], s5, bO);
                u64 s6 = pk(uB.z, uB.z); aE = ffma2(az2[6], s6, aE); bE = ffma2(ah2[6], s6, bE);
                u64 s7 = pk(uB.w, uB.w); aO = ffma2(az2[7], s7, aO); bO = ffma2(ah2[7], s7, bO);
                u64 a = fadd2(aE, aO);
                u64 b = fadd2(bE, bO);
                float ax, ay, bx, by;
                upk(a, ax, ay); upk(b, bx, by);
                float zx = fmaf(-0.5f, tanha(ax), 0.5f);
                float zy = fmaf(-0.5f, tanha(ay), 0.5f);
                float tx = tanha(bx);
                float ty = tanha(by);
                float pw = g_probs[p];
                hx = fmaf(pw * zx, tx, hx);
                hy = fmaf(pw * zy, ty, hy);
            }
            __syncwarp();
            hx = fmaxf(hx, 0.f);
            hy = fmaxf(hy, 0.f);
            *(float2*)&g_H[n * 64 + 2 * lane] = make_float2(hx, hy);
            psx += hx; pqx += hx * hx;
            psy += hy; pqy += hy * hy;
        }

        atomicAdd(&bsum[2 * lane],     psx);
        atomicAdd(&bsum[2 * lane + 1], psy);
        atomicAdd(&bsq[2 * lane],      pqx);
        atomicAdd(&bsq[2 * lane + 1],  pqy);
        __syncthreads();
        if (tid < 64) {
            atomicAdd(&g_sums[tid],  bsum[tid]);
            atomicAdd(&g_sumsq[tid], bsq[tid]);
        }
    }
    gbar(4);

    // ================= P4: BN-fold + packed out GEMM =======================
    // packed-f32x2 weights + duplicated-H smem broadcast: 5 issues per k-step
    {
        float* ss   = (float*)smraw;                       // 64
        float* st   = ss + 64;                             // 64
        float* sb   = st + 64;                             // 96
        u64*   sWp  = (u64*)(smraw + 1024);                // 2048 u64 = 16KB
        u64*   sWp2 = sWp + 2048;                          // 16KB
        float* hdup = (float*)(sWp2 + 2048);               // 8 warps * 128 floats
        int lane = tid & 31;
        int warp = tid >> 5;

        if (tid < 64) {
            float mean = g_sums[tid] * (1.0f / (float)NN);
            float var  = g_sumsq[tid] * (1.0f / (float)NN) - mean * mean;
            float sc = gamma[tid] * rsqrtf(var + 1e-5f);
            ss[tid] = sc;
            st[tid] = beta[tid] - mean * sc;
        }
        __syncthreads();
        if (tid < 96) {
            float s2 = g_bc[tid];
            for (int k = 0; k < 64; k++) s2 += st[k] * g_Wc[k * 96 + tid];
            sb[tid] = s2;
        }
        for (int idx = tid; idx < 2048; idx += 256) {
            int i = idx >> 5, l = idx & 31;
            float sc = ss[i];
            sWp[idx]  = pk(sc * g_Wc[i * 96 + l], sc * g_Wc[i * 96 + l + 32]);
            sWp2[idx] = pk(sc * g_Wc[i * 96 + l + 64], 0.f);
        }
        __syncthreads();

        float* hd = hdup + warp * 128;
        for (int n = bid * 8 + warp; n < NN; n += GB * 8) {
            float2 h2 = *(const float2*)&g_H[n * 64 + 2 * lane];
            float4 d4; d4.x = h2.x; d4.y = h2.x; d4.z = h2.y; d4.w = h2.y;
            __syncwarp();
            *(float4*)&hd[4 * lane] = d4;
            __syncwarp();

            u64 A = pk(sb[lane], sb[lane + 32]);
            u64 B = pk(sb[lane + 64], 0.f);
            #pragma unroll
            for (int i = 0; i < 64; i++) {
                u64 hv2 = *(const u64*)&hd[2 * i];         // (h_i, h_i) broadcast
                A = ffma2(sWp[i * 32 + lane],  hv2, A);
                B = ffma2(sWp2[i * 32 + lane], hv2, B);
            }
            float a0, a1, a2, dummy;
            upk(A, a0, a1); upk(B, a2, dummy);
            float* ob = out + n * 96;
            ob[lane] = a0; ob[lane + 32] = a1; ob[lane + 64] = a2;
        }
    }
}

// ---------------- launch ---------------------------------------------------
extern "C" void kernel_launch(void* const* d_in, const int* in_sizes, int n_in,
                              void* d_out, int out_size) {
    const float* x      = (const float*)d_in[0];
    const int*   ei     = (const int*)  d_in[1];
    const float* ew     = (const float*)d_in[2];
    const float* att    = (const float*)d_in[3];
    const float* conv_w = (const float*)d_in[4];
    const float* conv_b = (const float*)d_in[5];
    const float* lin_w  = (const float*)d_in[6];
    const float* lin_b  = (const float*)d_in[7];
    const float* gamma  = (const float*)d_in[8];
    const float* beta   = (const float*)d_in[9];
    const float* W1 = (const float*)d_in[10]; const float* b1 = (const float*)d_in[11];
    const float* W2 = (const float*)d_in[12]; const float* b2 = (const float*)d_in[13];
    const float* W3 = (const float*)d_in[14]; const float* b3 = (const float*)d_in[15];
    const float* W4 = (const float*)d_in[16]; const float* b4 = (const float*)d_in[17];
    const float* W5 = (const float*)d_in[18]; const float* b5 = (const float*)d_in[19];
    float* out = (float*)d_out;

    k_reset<<<1, 1>>>();
    k_mega<<<GB, 256>>>(x, ei, ew, att, conv_w, conv_b, lin_w, lin_b,
                        gamma, beta, W1, b1, W2, b2, W3, b3, W4, b4, W5, b5, out);
}

// round 16
// speedup vs baseline: 1.0471x; 1.0471x over previous
#include <cuda_runtime.h>

#define NN 50000
#define EE 800000
#define PP 12
#define NTILES 1563          // ceil(NN/32)
#define GB 444               // 148 SMs * 3 blocks — co-resident persistent grid
#define CAP 64               // bucket capacity (max in-degree ~40 for this graph)

typedef unsigned long long u64;

// ---------------- scratch (device globals; no allocation) ----------------
__device__ int    g_cnt[NN];             // in-edge count per node (padded to x4 after P2)
__device__ float  g_dinv[NN];
__device__ unsigned g_count;             // grid barrier counter
__device__ int2   g_rec[NN * CAP];       // bucketed records {row, ew-bits}
__device__ ulonglong2 g_xT32[NN * 24];   // fp32 features: [n][h][sub] float4
__device__ float  g_H[NN * 64];          // relu(H_accum)
__device__ float  g_sums[64];
__device__ float  g_sumsq[64];
__device__ float  g_Az[8 * 64], g_Ah[8 * 64];   // Az, cz pre-folded by 0.5
__device__ float  g_cz[64], g_ch[64];
__device__ float  g_probs[PP];
__device__ float  g_Wc[64 * 96], g_bc[96];

__device__ __forceinline__ float tanha(float x) {
    float r; asm("tanh.approx.f32 %0, %1;" : "=f"(r) : "f"(x)); return r;
}
__device__ __forceinline__ u64 pk(float x, float y) {
    u64 r; asm("mov.b64 %0, {%1, %2};" : "=l"(r) : "f"(x), "f"(y)); return r;
}
__device__ __forceinline__ void upk(u64 v, float& x, float& y) {
    asm("mov.b64 {%0, %1}, %2;" : "=f"(x), "=f"(y) : "l"(v));
}
__device__ __forceinline__ u64 ffma2(u64 a, u64 b, u64 c) {
    u64 d; asm("fma.rn.f32x2 %0, %1, %2, %3;" : "=l"(d) : "l"(a), "l"(b), "l"(c)); return d;
}
__device__ __forceinline__ u64 fadd2(u64 a, u64 b) {
    u64 d; asm("add.rn.f32x2 %0, %1, %2;" : "=l"(d) : "l"(a), "l"(b)); return d;
}
__device__ __forceinline__ u64 fmul2(u64 a, u64 b) {
    u64 d; asm("mul.rn.f32x2 %0, %1, %2;" : "=l"(d) : "l"(a), "l"(b)); return d;
}

// monotonic-counter grid barrier; k = 1,2,3,... within one kernel run
__device__ __forceinline__ void gbar(int k) {
    __syncthreads();
    if (threadIdx.x == 0) {
        __threadfence();
        atomicAdd(&g_count, 1u);
        while (*(volatile unsigned*)&g_count < (unsigned)(GB * k)) __nanosleep(32);
        __threadfence();
    }
    __syncthreads();
}

// ---------------- kernel A: reset barrier counter --------------------------
__global__ void k_reset() { g_count = 0u; }

// ---------------- kernel B: the whole pipeline, one persistent grid --------
__global__ void __launch_bounds__(256, 3) k_mega(
        const float* __restrict__ x,
        const int*   __restrict__ ei,
        const float* __restrict__ ew,
        const float* __restrict__ att,
        const float* __restrict__ conv_w, const float* __restrict__ conv_b,
        const float* __restrict__ lin_w,  const float* __restrict__ lin_b,
        const float* __restrict__ gamma,  const float* __restrict__ beta,
        const float* __restrict__ W1, const float* __restrict__ b1,
        const float* __restrict__ W2, const float* __restrict__ b2,
        const float* __restrict__ W3, const float* __restrict__ b3,
        const float* __restrict__ W4, const float* __restrict__ b4,
        const float* __restrict__ W5, const float* __restrict__ b5,
        float* __restrict__ out) {
    __shared__ __align__(16) char smraw[25600];
    int tid = threadIdx.x, bid = blockIdx.x;

    // ================= P0: init cnt + transpose x + fold weights ===========
    {
        for (int i = bid * 256 + tid; i < NN; i += GB * 256)
            g_cnt[i] = 0;

        float* s = (float*)smraw;                 // 32*96 floats = 12KB
        for (int tile = bid; tile < NTILES; tile += GB) {
            int blockNode = tile * 32;
            int lim = (NN - blockNode) * 96;
            __syncthreads();
            for (int i = tid; i < 32 * 96; i += 256)
                s[i] = (i < lim) ? x[blockNode * 96 + i] : 0.f;
            __syncthreads();
            #pragma unroll
            for (int k = 0; k < 3; k++) {
                int o = tid + k * 256;            // 0..767 = 32 nodes * 24 float4
                int ln = o / 24, l = o - ln * 24;
                int n = blockNode + ln;
                if (n < NN) {
                    int h = l / 12, sub = l - h * 12;
                    float4 v;
                    v.x = s[ln * 96 + (h * 4 + 0) * 12 + sub];
                    v.y = s[ln * 96 + (h * 4 + 1) * 12 + sub];
                    v.z = s[ln * 96 + (h * 4 + 2) * 12 + sub];
                    v.w = s[ln * 96 + (h * 4 + 3) * 12 + sub];
                    *(float4*)&g_xT32[n * 24 + h * 12 + sub] = v;
                }
            }
        }

        if (bid == GB - 1) {
            __syncthreads();
            float* sT1 = (float*)smraw;           // 2048 floats
            float* sT2 = sT1 + 2048;              // 1024
            float* sT3 = sT2 + 1024;              // 512
            float* sbb = sT3 + 512;               // 56

            if (tid == 0) {
                float m = -1e30f;
                for (int i = 0; i < PP; i++) m = fmaxf(m, att[i]);
                float e[PP], ssum = 0.f;
                for (int i = 0; i < PP; i++) { e[i] = __expf(att[i] - m); ssum += e[i]; }
                for (int i = 0; i < PP; i++) g_probs[i] = e[i] / ssum;
            }
            for (int idx = tid; idx < 8 * 64; idx += 256) {
                int i = idx >> 6, j = idx & 63;
                float az = 0.f, ah = 0.f;
                for (int k = 0; k < 64; k++) {
                    az += conv_w[0 * 512 + i * 64 + k] * lin_w[0 * 8192 + k * 64 + j];
                    ah += conv_w[2 * 512 + i * 64 + k] * lin_w[2 * 8192 + k * 64 + j];
                }
                g_Az[idx] = 0.5f * az; g_Ah[idx] = ah;
            }
            for (int j = tid; j < 64; j += 256) {
                float cz = lin_b[0 * 64 + j], ch = lin_b[2 * 64 + j];
                for (int k = 0; k < 64; k++) {
                    cz += conv_b[0 * 64 + k] * lin_w[0 * 8192 + k * 64 + j];
                    ch += conv_b[2 * 64 + k] * lin_w[2 * 8192 + k * 64 + j];
                }
                g_cz[j] = 0.5f * cz; g_ch[j] = ch;
                g_sums[j] = 0.f; g_sumsq[j] = 0.f;
            }
            for (int idx = tid; idx < 64 * 32; idx += 256) {
                int i = idx >> 5, j = idx & 31; float s2 = 0.f;
                for (int k = 0; k < 64; k++) s2 += W1[i * 64 + k] * W2[k * 32 + j];
                sT1[idx] = s2;
            }
            if (tid < 32) { float s2 = b2[tid]; for (int k = 0; k < 64; k++) s2 += b1[k] * W2[k * 32 + tid]; sbb[tid] = s2; }
            __syncthreads();
            for (int idx = tid; idx < 64 * 16; idx += 256) {
                int i = idx >> 4, j = idx & 15; float s2 = 0.f;
                for (int k = 0; k < 32; k++) s2 += sT1[i * 32 + k] * W3[k * 16 + j];
                sT2[idx] = s2;
            }
            if (tid < 16) { float s2 = b3[tid]; for (int k = 0; k < 32; k++) s2 += sbb[k] * W3[k * 16 + tid]; sbb[32 + tid] = s2; }
            __syncthreads();
            for (int idx = tid; idx < 64 * 8; idx += 256) {
                int i = idx >> 3, j = idx & 7; float s2 = 0.f;
                for (int k = 0; k < 16; k++) s2 += sT2[i * 16 + k] * W4[k * 8 + j];
                sT3[idx] = s2;
            }
            if (tid < 8) { float s2 = b4[tid]; for (int k = 0; k < 16; k++) s2 += sbb[32 + k] * W4[k * 8 + tid]; sbb[48 + tid] = s2; }
            __syncthreads();
            for (int idx = tid; idx < 64 * 96; idx += 256) {
                int i = idx / 96, j = idx - i * 96; float s2 = 0.f;
                for (int k = 0; k < 8; k++) s2 += sT3[i * 8 + k] * W5[k * 96 + j];
                g_Wc[idx] = s2;
            }
            for (int j = tid; j < 96; j += 256) {
                float s2 = b5[j];
                for (int k = 0; k < 8; k++) s2 += sbb[48 + k] * W5[k * 96 + j];
                g_bc[j] = s2;
            }
        }
    }
    gbar(1);

    // ================= P1: bucket fill {row, ew} (2 edges/iter) ============
    for (int e = (bid * 256 + tid) * 2; e < EE; e += GB * 256 * 2) {
        int2 rows = *(const int2*)&ei[e];
        int2 cols = *(const int2*)&ei[EE + e];
        float2 w = *(const float2*)&ew[e];
        int p0 = atomicAdd(&g_cnt[cols.x], 1);
        if (p0 < CAP) g_rec[cols.x * CAP + p0] = make_int2(rows.x, __float_as_int(w.x));
        int p1 = atomicAdd(&g_cnt[cols.y], 1);
        if (p1 < CAP) g_rec[cols.y * CAP + p1] = make_int2(rows.y, __float_as_int(w.y));
    }
    gbar(2);

    // ================= P2: degree -> dinv, pad bucket to multiple of 4 =====
    for (int n = bid * 256 + tid; n < NN; n += GB * 256) {
        int cnt = g_cnt[n];
        if (cnt > CAP) cnt = CAP;
        int2* rec = &g_rec[n * CAP];
        float s = 1.0f;                          // self-loop weight
        for (int j = 0; j < cnt; j++) s += __int_as_float(rec[j].y);
        g_dinv[n] = rsqrtf(s);
        int cnt4 = (cnt + 3) & ~3;               // pad with zero-weight self records
        for (int j = cnt; j < cnt4; j++) rec[j] = make_int2(n, 0);
        g_cnt[n] = cnt4;
    }
    gbar(3);

    // ================= P3: fused gather + GRU + BN stats ===================
    // 8 lanes per edge, 4 edges per iteration, all 32 lanes useful.
    {
        float* bsum = (float*)smraw;             // 64
        float* bsq  = bsum + 64;                 // 64
        float* tw   = bsq + 64;                  // 8 warps * 96
        if (tid < 64) { bsum[tid] = 0.f; bsq[tid] = 0.f; }
        __syncthreads();

        int lane = tid & 31;
        int warp = tid >> 5;
        int g  = lane >> 3;                      // edge-in-quad 0..3
        int l3 = (lane & 7) * 3;                 // first chunk (0,3,...,21)
        float* twr = tw + warp * 96;             // linear layout: chunk c -> floats [4c..4c+3]

        u64 az2[8], ah2[8];
        #pragma unroll
        for (int i = 0; i < 8; i++) {
            az2[i] = *(const u64*)&g_Az[i * 64 + 2 * lane];
            ah2[i] = *(const u64*)&g_Ah[i * 64 + 2 * lane];
        }
        u64 cz2 = *(const u64*)&g_cz[2 * lane];
        u64 ch2 = *(const u64*)&g_ch[2 * lane];

        float psx = 0.f, psy = 0.f, pqx = 0.f, pqy = 0.f;

        for (int n = bid * 8 + warp; n < NN; n += GB * 8) {
            float dn = g_dinv[n];
            int cnt4 = g_cnt[n];                 // padded to x4, <= CAP
            int start = n * CAP;

            u64 a0 = 0, a1 = 0, a2 = 0, a3 = 0, a4 = 0, a5 = 0;
            {   // self term, quarter-coeff in every group (sums to dn over 4 groups)
                const ulonglong2* bp = g_xT32 + n * 24 + l3;
                ulonglong2 v0 = bp[0], v1 = bp[1], v2 = bp[2];
                float fq = 0.25f * dn;
                u64 c = pk(fq, fq);
                a0 = ffma2(v0.x, c, a0); a1 = ffma2(v0.y, c, a1);
                a2 = ffma2(v1.x, c, a2); a3 = ffma2(v1.y, c, a3);
                a4 = ffma2(v2.x, c, a4); a5 = ffma2(v2.y, c, a5);
            }

            #pragma unroll 2
            for (int e = start; e < start + cnt4; e += 4) {
                int2 r = g_rec[e + g];
                float f = __int_as_float(r.y) * g_dinv[r.x];
                const ulonglong2* bp = g_xT32 + r.x * 24 + l3;
                ulonglong2 v0 = bp[0], v1 = bp[1], v2 = bp[2];
                u64 c = pk(f, f);
                a0 = ffma2(v0.x, c, a0); a1 = ffma2(v0.y, c, a1);
                a2 = ffma2(v1.x, c, a2); a3 = ffma2(v1.y, c, a3);
                a4 = ffma2(v2.x, c, a4); a5 = ffma2(v2.y, c, a5);
            }

            // reduce over 4 edge groups (lanes l, l+8, l+16, l+24), apply dinv[n]
            a0 = fadd2(a0, __shfl_down_sync(0xffffffffu, a0, 16));
            a1 = fadd2(a1, __shfl_down_sync(0xffffffffu, a1, 16));
            a2 = fadd2(a2, __shfl_down_sync(0xffffffffu, a2, 16));
            a3 = fadd2(a3, __shfl_down_sync(0xffffffffu, a3, 16));
            a4 = fadd2(a4, __shfl_down_sync(0xffffffffu, a4, 16));
            a5 = fadd2(a5, __shfl_down_sync(0xffffffffu, a5, 16));
            a0 = fadd2(a0, __shfl_down_sync(0xffffffffu, a0, 8));
            a1 = fadd2(a1, __shfl_down_sync(0xffffffffu, a1, 8));
            a2 = fadd2(a2, __shfl_down_sync(0xffffffffu, a2, 8));
            a3 = fadd2(a3, __shfl_down_sync(0xffffffffu, a3, 8));
            a4 = fadd2(a4, __shfl_down_sync(0xffffffffu, a4, 8));
            a5 = fadd2(a5, __shfl_down_sync(0xffffffffu, a5, 8));
            u64 d2 = pk(dn, dn);
            a0 = fmul2(a0, d2); a1 = fmul2(a1, d2);
            a2 = fmul2(a2, d2); a3 = fmul2(a3, d2);
            a4 = fmul2(a4, d2); a5 = fmul2(a5, d2);

            __syncwarp();
            if (lane < 8) {
                ulonglong2* dst = (ulonglong2*)twr;   // chunk c at dst[c]
                dst[l3 + 0] = make_ulonglong2(a0, a1);
                dst[l3 + 1] = make_ulonglong2(a2, a3);
                dst[l3 + 2] = make_ulonglong2(a4, a5);
            }
            __syncwarp();

            float hx = 0.f, hy = 0.f;
            #pragma unroll
            for (int p = 0; p < PP; p++) {
                float4 uA = *(const float4*)&twr[p * 4];           // chunk p (h0)
                float4 uB = *(const float4*)&twr[(12 + p) * 4];    // chunk 12+p (h1)
                // split even/odd chains: depth 8 -> 4, ILP 2 -> 4
                u64 aE = cz2, aO = 0, bE = ch2, bO = 0;
                u64 s0 = pk(uA.x, uA.x); aE = ffma2(az2[0], s0, aE); bE = ffma2(ah2[0], s0, bE);
                u64 s1 = pk(uA.y, uA.y); aO = ffma2(az2[1], s1, aO); bO = ffma2(ah2[1], s1, bO);
                u64 s2 = pk(uA.z, uA.z); aE = ffma2(az2[2], s2, aE); bE = ffma2(ah2[2], s2, bE);
                u64 s3 = pk(uA.w, uA.w); aO = ffma2(az2[3], s3, aO); bO = ffma2(ah2[3], s3, bO);
                u64 s4 = pk(uB.x, uB.x); aE = ffma2(az2[4], s4, aE); bE = ffma2(ah2[4], s4, bE);
                u64 s5 = pk(uB.y, uB.y); aO = ffma2(az2[5], s5, aO); bO = ffma2(ah2[5], s5, bO);
                u64 s6 = pk(uB.z, uB.z); aE = ffma2(az2[6], s6, aE); bE = ffma2(ah2[6], s6, bE);
                u64 s7 = pk(uB.w, uB.w); aO = ffma2(az2[7], s7, aO); bO = ffma2(ah2[7], s7, bO);
                u64 a = fadd2(aE, aO);
                u64 b = fadd2(bE, bO);
                float ax, ay, bx, by;
                upk(a, ax, ay); upk(b, bx, by);
                float zx = fmaf(-0.5f, tanha(ax), 0.5f);
                float zy = fmaf(-0.5f, tanha(ay), 0.5f);
                float tx = tanha(bx);
                float ty = tanha(by);
                float pw = g_probs[p];
                hx = fmaf(pw * zx, tx, hx);
                hy = fmaf(pw * zy, ty, hy);
            }
            __syncwarp();
            hx = fmaxf(hx, 0.f);
            hy = fmaxf(hy, 0.f);
            *(float2*)&g_H[n * 64 + 2 * lane] = make_float2(hx, hy);
            psx += hx; pqx += hx * hx;
            psy += hy; pqy += hy * hy;
        }

        atomicAdd(&bsum[2 * lane],     psx);
        atomicAdd(&bsum[2 * lane + 1], psy);
        atomicAdd(&bsq[2 * lane],      pqx);
        atomicAdd(&bsq[2 * lane + 1],  pqy);
        __syncthreads();
        if (tid < 64) {
            atomicAdd(&g_sums[tid],  bsum[tid]);
            atomicAdd(&g_sumsq[tid], bsq[tid]);
        }
    }
    gbar(4);

    // ================= P4: BN-fold + out = relu(H) @ W_eff + b_eff =========
    {
        float* sW = (float*)smraw;               // 64*96
        float* sb = sW + 64 * 96;                // 96
        float* ss = sb + 96;                     // 64
        float* st = ss + 64;                     // 64
        if (tid < 64) {
            float mean = g_sums[tid] * (1.0f / (float)NN);
            float var  = g_sumsq[tid] * (1.0f / (float)NN) - mean * mean;
            float sc = gamma[tid] * rsqrtf(var + 1e-5f);
            ss[tid] = sc;
            st[tid] = beta[tid] - mean * sc;
        }
        __syncthreads();
        for (int idx = tid; idx < 64 * 96; idx += 256)
            sW[idx] = ss[idx / 96] * g_Wc[idx];
        if (tid < 96) {
            float s2 = g_bc[tid];
            for (int k = 0; k < 64; k++) s2 += st[k] * g_Wc[k * 96 + tid];
            sb[tid] = s2;
        }
        __syncthreads();

        int lane = tid & 31;
        int warp = tid >> 5;
        for (int n = bid * 8 + warp; n < NN; n += GB * 8) {
            float2 h2 = *(const float2*)&g_H[n * 64 + 2 * lane];
            float a0 = sb[lane], a1 = sb[lane + 32], a2 = sb[lane + 64];
            #pragma unroll
            for (int i = 0; i < 64; i++) {
                float hv = __shfl_sync(0xffffffffu, (i & 1) ? h2.y : h2.x, i >> 1);
                const float* wr = &sW[i * 96];
                a0 = fmaf(hv, wr[lane],      a0);
                a1 = fmaf(hv, wr[lane + 32], a1);
                a2 = fmaf(hv, wr[lane + 64], a2);
            }
            float* ob = out + n * 96;
            ob[lane] = a0; ob[lane + 32] = a1; ob[lane + 64] = a2;
        }
    }
}

// ---------------- launch ---------------------------------------------------
extern "C" void kernel_launch(void* const* d_in, const int* in_sizes, int n_in,
                              void* d_out, int out_size) {
    const float* x      = (const float*)d_in[0];
    const int*   ei     = (const int*)  d_in[1];
    const float* ew     = (const float*)d_in[2];
    const float* att    = (const float*)d_in[3];
    const float* conv_w = (const float*)d_in[4];
    const float* conv_b = (const float*)d_in[5];
    const float* lin_w  = (const float*)d_in[6];
    const float* lin_b  = (const float*)d_in[7];
    const float* gamma  = (const float*)d_in[8];
    const float* beta   = (const float*)d_in[9];
    const float* W1 = (const float*)d_in[10]; const float* b1 = (const float*)d_in[11];
    const float* W2 = (const float*)d_in[12]; const float* b2 = (const float*)d_in[13];
    const float* W3 = (const float*)d_in[14]; const float* b3 = (const float*)d_in[15];
    const float* W4 = (const float*)d_in[16]; const float* b4 = (const float*)d_in[17];
    const float* W5 = (const float*)d_in[18]; const float* b5 = (const float*)d_in[19];
    float* out = (float*)d_out;

    k_reset<<<1, 1>>>();
    k_mega<<<GB, 256>>>(x, ei, ew, att, conv_w, conv_b, lin_w, lin_b,
                        gamma, beta, W1, b1, W2, b2, W3, b3, W4, b4, W5, b5, out);
}

// round 17
// speedup vs baseline: 1.1352x; 1.0841x over previous
#include <cuda_runtime.h>

#define NN 50000
#define EE 800000
#define PP 12
#define NTILES 1563          // ceil(NN/32)
#define GB 444               // 148 SMs * 3 blocks — co-resident persistent grid
#define CAP 64               // bucket capacity (max in-degree ~40 for this graph)

typedef unsigned long long u64;

// ---------------- scratch (device globals; no allocation) ----------------
__device__ int    g_cnt[NN];             // in-edge count per node (padded to x4 after P2)
__device__ float  g_dinv[NN];
__device__ unsigned g_count;             // grid barrier counter
__device__ int2   g_rec[NN * CAP];       // bucketed records {row, ew-bits}
__device__ ulonglong2 g_xT32[NN * 24];   // fp32 features: [n][h][sub] float4
__device__ float  g_H[NN * 64];          // relu(H_accum)
__device__ float  g_sums[64];
__device__ float  g_sumsq[64];
__device__ float  g_Az[8 * 64], g_Ah[8 * 64];   // Az, cz pre-folded by 0.5
__device__ float  g_cz[64], g_ch[64];
__device__ float  g_probs[PP];
__device__ float  g_Wc[64 * 96], g_bc[96];

__device__ __forceinline__ float tanha(float x) {
    float r; asm("tanh.approx.f32 %0, %1;" : "=f"(r) : "f"(x)); return r;
}
__device__ __forceinline__ u64 pk(float x, float y) {
    u64 r; asm("mov.b64 %0, {%1, %2};" : "=l"(r) : "f"(x), "f"(y)); return r;
}
__device__ __forceinline__ void upk(u64 v, float& x, float& y) {
    asm("mov.b64 {%0, %1}, %2;" : "=f"(x), "=f"(y) : "l"(v));
}
__device__ __forceinline__ u64 ffma2(u64 a, u64 b, u64 c) {
    u64 d; asm("fma.rn.f32x2 %0, %1, %2, %3;" : "=l"(d) : "l"(a), "l"(b), "l"(c)); return d;
}
__device__ __forceinline__ u64 fadd2(u64 a, u64 b) {
    u64 d; asm("add.rn.f32x2 %0, %1, %2;" : "=l"(d) : "l"(a), "l"(b)); return d;
}
__device__ __forceinline__ u64 fmul2(u64 a, u64 b) {
    u64 d; asm("mul.rn.f32x2 %0, %1, %2;" : "=l"(d) : "l"(a), "l"(b)); return d;
}

// monotonic-counter grid barrier; k = 1,2,3,... within one kernel run
__device__ __forceinline__ void gbar(int k) {
    __syncthreads();
    if (threadIdx.x == 0) {
        __threadfence();
        atomicAdd(&g_count, 1u);
        while (*(volatile unsigned*)&g_count < (unsigned)(GB * k)) __nanosleep(32);
        __threadfence();
    }
    __syncthreads();
}

// ---------------- kernel A: reset barrier counter --------------------------
__global__ void k_reset() { g_count = 0u; }

// ---------------- kernel B: the whole pipeline, one persistent grid --------
__global__ void __launch_bounds__(256, 3) k_mega(
        const float* __restrict__ x,
        const int*   __restrict__ ei,
        const float* __restrict__ ew,
        const float* __restrict__ att,
        const float* __restrict__ conv_w, const float* __restrict__ conv_b,
        const float* __restrict__ lin_w,  const float* __restrict__ lin_b,
        const float* __restrict__ gamma,  const float* __restrict__ beta,
        const float* __restrict__ W1, const float* __restrict__ b1,
        const float* __restrict__ W2, const float* __restrict__ b2,
        const float* __restrict__ W3, const float* __restrict__ b3,
        const float* __restrict__ W4, const float* __restrict__ b4,
        const float* __restrict__ W5, const float* __restrict__ b5,
        float* __restrict__ out) {
    __shared__ __align__(16) char smraw[25600];
    int tid = threadIdx.x, bid = blockIdx.x;

    // ================= P0: init cnt (tiny) =================================
    for (int i = bid * 256 + tid; i < NN; i += GB * 256)
        g_cnt[i] = 0;
    gbar(1);

    // ================= P1: transpose + fill + fold, overlapped =============
    {
        // sub-tasks (data-independent): parity staggers pipe usage
        bool doFillFirst = (bid & 1);

        // ---- fill lambda-ish inline (all blocks) ----
        #define DO_FILL()                                                          \
        for (int e = (bid * 256 + tid) * 2; e < EE; e += GB * 256 * 2) {           \
            int2 rows = *(const int2*)&ei[e];                                      \
            int2 cols = *(const int2*)&ei[EE + e];                                 \
            float2 w = *(const float2*)&ew[e];                                     \
            int p0 = atomicAdd(&g_cnt[cols.x], 1);                                 \
            if (p0 < CAP) g_rec[cols.x * CAP + p0] = make_int2(rows.x, __float_as_int(w.x)); \
            int p1 = atomicAdd(&g_cnt[cols.y], 1);                                 \
            if (p1 < CAP) g_rec[cols.y * CAP + p1] = make_int2(rows.y, __float_as_int(w.y)); \
        }

        // ---- transpose lambda-ish inline (blocks 0..GB-2) ----
        #define DO_TRANSPOSE()                                                     \
        if (bid < GB - 1) {                                                        \
            float* s = (float*)smraw;                                              \
            for (int tile = bid; tile < NTILES; tile += GB - 1) {                  \
                int blockNode = tile * 32;                                         \
                int lim = (NN - blockNode) * 96;                                   \
                __syncthreads();                                                   \
                for (int i = tid; i < 32 * 96; i += 256)                           \
                    s[i] = (i < lim) ? x[blockNode * 96 + i] : 0.f;                \
                __syncthreads();                                                   \
                _Pragma("unroll")                                                  \
                for (int k = 0; k < 3; k++) {                                      \
                    int o = tid + k * 256;                                         \
                    int ln = o / 24, l = o - ln * 24;                              \
                    int n = blockNode + ln;                                        \
                    if (n < NN) {                                                  \
                        int h = l / 12, sub = l - h * 12;                          \
                        float4 v;                                                  \
                        v.x = s[ln * 96 + (h * 4 + 0) * 12 + sub];                 \
                        v.y = s[ln * 96 + (h * 4 + 1) * 12 + sub];                 \
                        v.z = s[ln * 96 + (h * 4 + 2) * 12 + sub];                 \
                        v.w = s[ln * 96 + (h * 4 + 3) * 12 + sub];                 \
                        *(float4*)&g_xT32[n * 24 + h * 12 + sub] = v;              \
                    }                                                              \
                }                                                                  \
            }                                                                      \
        }

        if (bid == GB - 1) {
            // ---- fold-only block: small linear algebra, then its fill share ----
            float* sT1 = (float*)smraw;           // 2048 floats
            float* sT2 = sT1 + 2048;              // 1024
            float* sT3 = sT2 + 1024;              // 512
            float* sbb = sT3 + 512;               // 56

            if (tid == 0) {
                float m = -1e30f;
                for (int i = 0; i < PP; i++) m = fmaxf(m, att[i]);
                float e[PP], ssum = 0.f;
                for (int i = 0; i < PP; i++) { e[i] = __expf(att[i] - m); ssum += e[i]; }
                for (int i = 0; i < PP; i++) g_probs[i] = e[i] / ssum;
            }
            for (int idx = tid; idx < 8 * 64; idx += 256) {
                int i = idx >> 6, j = idx & 63;
                float az = 0.f, ah = 0.f;
                for (int k = 0; k < 64; k++) {
                    az += conv_w[0 * 512 + i * 64 + k] * lin_w[0 * 8192 + k * 64 + j];
                    ah += conv_w[2 * 512 + i * 64 + k] * lin_w[2 * 8192 + k * 64 + j];
                }
                g_Az[idx] = 0.5f * az; g_Ah[idx] = ah;
            }
            for (int j = tid; j < 64; j += 256) {
                float cz = lin_b[0 * 64 + j], ch = lin_b[2 * 64 + j];
                for (int k = 0; k < 64; k++) {
                    cz += conv_b[0 * 64 + k] * lin_w[0 * 8192 + k * 64 + j];
                    ch += conv_b[2 * 64 + k] * lin_w[2 * 8192 + k * 64 + j];
                }
                g_cz[j] = 0.5f * cz; g_ch[j] = ch;
                g_sums[j] = 0.f; g_sumsq[j] = 0.f;
            }
            for (int idx = tid; idx < 64 * 32; idx += 256) {
                int i = idx >> 5, j = idx & 31; float s2 = 0.f;
                for (int k = 0; k < 64; k++) s2 += W1[i * 64 + k] * W2[k * 32 + j];
                sT1[idx] = s2;
            }
            if (tid < 32) { float s2 = b2[tid]; for (int k = 0; k < 64; k++) s2 += b1[k] * W2[k * 32 + tid]; sbb[tid] = s2; }
            __syncthreads();
            for (int idx = tid; idx < 64 * 16; idx += 256) {
                int i = idx >> 4, j = idx & 15; float s2 = 0.f;
                for (int k = 0; k < 32; k++) s2 += sT1[i * 32 + k] * W3[k * 16 + j];
                sT2[idx] = s2;
            }
            if (tid < 16) { float s2 = b3[tid]; for (int k = 0; k < 32; k++) s2 += sbb[k] * W3[k * 16 + tid]; sbb[32 + tid] = s2; }
            __syncthreads();
            for (int idx = tid; idx < 64 * 8; idx += 256) {
                int i = idx >> 3, j = idx & 7; float s2 = 0.f;
                for (int k = 0; k < 16; k++) s2 += sT2[i * 16 + k] * W4[k * 8 + j];
                sT3[idx] = s2;
            }
            if (tid < 8) { float s2 = b4[tid]; for (int k = 0; k < 16; k++) s2 += sbb[32 + k] * W4[k * 8 + tid]; sbb[48 + tid] = s2; }
            __syncthreads();
            for (int idx = tid; idx < 64 * 96; idx += 256) {
                int i = idx / 96, j = idx - i * 96; float s2 = 0.f;
                for (int k = 0; k < 8; k++) s2 += sT3[i * 8 + k] * W5[k * 96 + j];
                g_Wc[idx] = s2;
            }
            for (int j = tid; j < 96; j += 256) {
                float s2 = b5[j];
                for (int k = 0; k < 8; k++) s2 += sbb[48 + k] * W5[k * 96 + j];
                g_bc[j] = s2;
            }
            DO_FILL();
        } else if (doFillFirst) {
            DO_FILL();
            DO_TRANSPOSE();
        } else {
            DO_TRANSPOSE();
            DO_FILL();
        }
        #undef DO_FILL
        #undef DO_TRANSPOSE
    }
    gbar(2);

    // ================= P2: degree -> dinv, pad bucket to multiple of 4 =====
    for (int n = bid * 256 + tid; n < NN; n += GB * 256) {
        int cnt = g_cnt[n];
        if (cnt > CAP) cnt = CAP;
        int2* rec = &g_rec[n * CAP];
        float s = 1.0f;                          // self-loop weight
        for (int j = 0; j < cnt; j++) s += __int_as_float(rec[j].y);
        g_dinv[n] = rsqrtf(s);
        int cnt4 = (cnt + 3) & ~3;               // pad with zero-weight self records
        for (int j = cnt; j < cnt4; j++) rec[j] = make_int2(n, 0);
        g_cnt[n] = cnt4;
    }
    gbar(3);

    // ================= P3: fused gather + GRU + BN stats ===================
    // 8 lanes per edge, 4 edges per iteration, all 32 lanes useful.
    {
        float* bsum = (float*)smraw;             // 64
        float* bsq  = bsum + 64;                 // 64
        float* tw   = bsq + 64;                  // 8 warps * 96
        if (tid < 64) { bsum[tid] = 0.f; bsq[tid] = 0.f; }
        __syncthreads();

        int lane = tid & 31;
        int warp = tid >> 5;
        int g  = lane >> 3;                      // edge-in-quad 0..3
        int l3 = (lane & 7) * 3;                 // first chunk (0,3,...,21)
        float* twr = tw + warp * 96;             // linear layout: chunk c -> floats [4c..4c+3]

        u64 az2[8], ah2[8];
        #pragma unroll
        for (int i = 0; i < 8; i++) {
            az2[i] = *(const u64*)&g_Az[i * 64 + 2 * lane];
            ah2[i] = *(const u64*)&g_Ah[i * 64 + 2 * lane];
        }
        u64 cz2 = *(const u64*)&g_cz[2 * lane];
        u64 ch2 = *(const u64*)&g_ch[2 * lane];

        float psx = 0.f, psy = 0.f, pqx = 0.f, pqy = 0.f;

        for (int n = bid * 8 + warp; n < NN; n += GB * 8) {
            float dn = g_dinv[n];
            int cnt4 = g_cnt[n];                 // padded to x4, <= CAP
            int start = n * CAP;

            u64 a0 = 0, a1 = 0, a2 = 0, a3 = 0, a4 = 0, a5 = 0;
            {   // self term, quarter-coeff in every group (sums to dn over 4 groups)
                const ulonglong2* bp = g_xT32 + n * 24 + l3;
                ulonglong2 v0 = bp[0], v1 = bp[1], v2 = bp[2];
                float fq = 0.25f * dn;
                u64 c = pk(fq, fq);
                a0 = ffma2(v0.x, c, a0); a1 = ffma2(v0.y, c, a1);
                a2 = ffma2(v1.x, c, a2); a3 = ffma2(v1.y, c, a3);
                a4 = ffma2(v2.x, c, a4); a5 = ffma2(v2.y, c, a5);
            }

            for (int e = start; e < start + cnt4; e += 4) {
                int2 r = g_rec[e + g];
                float f = __int_as_float(r.y) * g_dinv[r.x];
                const ulonglong2* bp = g_xT32 + r.x * 24 + l3;
                ulonglong2 v0 = bp[0], v1 = bp[1], v2 = bp[2];
                u64 c = pk(f, f);
                a0 = ffma2(v0.x, c, a0); a1 = ffma2(v0.y, c, a1);
                a2 = ffma2(v1.x, c, a2); a3 = ffma2(v1.y, c, a3);
                a4 = ffma2(v2.x, c, a4); a5 = ffma2(v2.y, c, a5);
            }

            // reduce over 4 edge groups (lanes l, l+8, l+16, l+24), apply dinv[n]
            a0 = fadd2(a0, __shfl_down_sync(0xffffffffu, a0, 16));
            a1 = fadd2(a1, __shfl_down_sync(0xffffffffu, a1, 16));
            a2 = fadd2(a2, __shfl_down_sync(0xffffffffu, a2, 16));
            a3 = fadd2(a3, __shfl_down_sync(0xffffffffu, a3, 16));
            a4 = fadd2(a4, __shfl_down_sync(0xffffffffu, a4, 16));
            a5 = fadd2(a5, __shfl_down_sync(0xffffffffu, a5, 16));
            a0 = fadd2(a0, __shfl_down_sync(0xffffffffu, a0, 8));
            a1 = fadd2(a1, __shfl_down_sync(0xffffffffu, a1, 8));
            a2 = fadd2(a2, __shfl_down_sync(0xffffffffu, a2, 8));
            a3 = fadd2(a3, __shfl_down_sync(0xffffffffu, a3, 8));
            a4 = fadd2(a4, __shfl_down_sync(0xffffffffu, a4, 8));
            a5 = fadd2(a5, __shfl_down_sync(0xffffffffu, a5, 8));
            u64 d2 = pk(dn, dn);
            a0 = fmul2(a0, d2); a1 = fmul2(a1, d2);
            a2 = fmul2(a2, d2); a3 = fmul2(a3, d2);
            a4 = fmul2(a4, d2); a5 = fmul2(a5, d2);

            __syncwarp();
            if (lane < 8) {
                ulonglong2* dst = (ulonglong2*)twr;   // chunk c at dst[c]
                dst[l3 + 0] = make_ulonglong2(a0, a1);
                dst[l3 + 1] = make_ulonglong2(a2, a3);
                dst[l3 + 2] = make_ulonglong2(a4, a5);
            }
            __syncwarp();

            float hx = 0.f, hy = 0.f;
            #pragma unroll
            for (int p = 0; p < PP; p++) {
                float4 uA = *(const float4*)&twr[p * 4];           // chunk p (h0)
                float4 uB = *(const float4*)&twr[(12 + p) * 4];    // chunk 12+p (h1)
                // split even/odd chains: depth 8 -> 4, ILP 2 -> 4
                u64 aE = cz2, aO = 0, bE = ch2, bO = 0;
                u64 s0 = pk(uA.x, uA.x); aE = ffma2(az2[0], s0, aE); bE = ffma2(ah2[0], s0, bE);
                u64 s1 = pk(uA.y, uA.y); aO = ffma2(az2[1], s1, aO); bO = ffma2(ah2[1], s1, bO);
                u64 s2 = pk(uA.z, uA.z); aE = ffma2(az2[2], s2, aE); bE = ffma2(ah2[2], s2, bE);
                u64 s3 = pk(uA.w, uA.w); aO = ffma2(az2[3], s3, aO); bO = ffma2(ah2[3], s3, bO);
                u64 s4 = pk(uB.x, uB.x); aE = ffma2(az2[4], s4, aE); bE = ffma2(ah2[4], s4, bE);
                u64 s5 = pk(uB.y, uB.y); aO = ffma2(az2[5], s5, aO); bO = ffma2(ah2[5], s5, bO);
                u64 s6 = pk(uB.z, uB.z); aE = ffma2(az2[6], s6, aE); bE = ffma2(ah2[6], s6, bE);
                u64 s7 = pk(uB.w, uB.w); aO = ffma2(az2[7], s7, aO); bO = ffma2(ah2[7], s7, bO);
                u64 a = fadd2(aE, aO);
                u64 b = fadd2(bE, bO);
                float ax, ay, bx, by;
                upk(a, ax, ay); upk(b, bx, by);
                float zx = fmaf(-0.5f, tanha(ax), 0.5f);
                float zy = fmaf(-0.5f, tanha(ay), 0.5f);
                float tx = tanha(bx);
                float ty = tanha(by);
                float pw = g_probs[p];
                hx = fmaf(pw * zx, tx, hx);
                hy = fmaf(pw * zy, ty, hy);
            }
            __syncwarp();
            hx = fmaxf(hx, 0.f);
            hy = fmaxf(hy, 0.f);
            *(float2*)&g_H[n * 64 + 2 * lane] = make_float2(hx, hy);
            psx += hx; pqx += hx * hx;
            psy += hy; pqy += hy * hy;
        }

        atomicAdd(&bsum[2 * lane],     psx);
        atomicAdd(&bsum[2 * lane + 1], psy);
        atomicAdd(&bsq[2 * lane],      pqx);
        atomicAdd(&bsq[2 * lane + 1],  pqy);
        __syncthreads();
        if (tid < 64) {
            atomicAdd(&g_sums[tid],  bsum[tid]);
            atomicAdd(&g_sumsq[tid], bsq[tid]);
        }
    }
    gbar(4);

    // ================= P4: BN-fold + out = relu(H) @ W_eff + b_eff =========
    {
        float* sW = (float*)smraw;               // 64*96
        float* sb = sW + 64 * 96;                // 96
        float* ss = sb + 96;                     // 64
        float* st = ss + 64;                     // 64
        if (tid < 64) {
            float mean = g_sums[tid] * (1.0f / (float)NN);
            float var  = g_sumsq[tid] * (1.0f / (float)NN) - mean * mean;
            float sc = gamma[tid] * rsqrtf(var + 1e-5f);
            ss[tid] = sc;
            st[tid] = beta[tid] - mean * sc;
        }
        __syncthreads();
        for (int idx = tid; idx < 64 * 96; idx += 256)
            sW[idx] = ss[idx / 96] * g_Wc[idx];
        if (tid < 96) {
            float s2 = g_bc[tid];
            for (int k = 0; k < 64; k++) s2 += st[k] * g_Wc[k * 96 + tid];
            sb[tid] = s2;
        }
        __syncthreads();

        int lane = tid & 31;
        int warp = tid >> 5;
        for (int n = bid * 8 + warp; n < NN; n += GB * 8) {
            float2 h2 = *(const float2*)&g_H[n * 64 + 2 * lane];
            float a0 = sb[lane], a1 = sb[lane + 32], a2 = sb[lane + 64];
            #pragma unroll
            for (int i = 0; i < 64; i++) {
                float hv = __shfl_sync(0xffffffffu, (i & 1) ? h2.y : h2.x, i >> 1);
                const float* wr = &sW[i * 96];
                a0 = fmaf(hv, wr[lane],      a0);
                a1 = fmaf(hv, wr[lane + 32], a1);
                a2 = fmaf(hv, wr[lane + 64], a2);
            }
            float* ob = out + n * 96;
            ob[lane] = a0; ob[lane + 32] = a1; ob[lane + 64] = a2;
        }
    }
}

// ---------------- launch ---------------------------------------------------
extern "C" void kernel_launch(void* const* d_in, const int* in_sizes, int n_in,
                              void* d_out, int out_size) {
    const float* x      = (const float*)d_in[0];
    const int*   ei     = (const int*)  d_in[1];
    const float* ew     = (const float*)d_in[2];
    const float* att    = (const float*)d_in[3];
    const float* conv_w = (const float*)d_in[4];
    const float* conv_b = (const float*)d_in[5];
    const float* lin_w  = (const float*)d_in[6];
    const float* lin_b  = (const float*)d_in[7];
    const float* gamma  = (const float*)d_in[8];
    const float* beta   = (const float*)d_in[9];
    const float* W1 = (const float*)d_in[10]; const float* b1 = (const float*)d_in[11];
    const float* W2 = (const float*)d_in[12]; const float* b2 = (const float*)d_in[13];
    const float* W3 = (const float*)d_in[14]; const float* b3 = (const float*)d_in[15];
    const float* W4 = (const float*)d_in[16]; const float* b4 = (const float*)d_in[17];
    const float* W5 = (const float*)d_in[18]; const float* b5 = (const float*)d_in[19];
    float* out = (float*)d_out;

    k_reset<<<1, 1>>>();
    k_mega<<<GB, 256>>>(x, ei, ew, att, conv_w, conv_b, lin_w, lin_b,
                        gamma, beta, W1, b1, W2, b2, W3, b3, W4, b4, W5, b5, out);
}